// round 4
// baseline (speedup 1.0000x reference)
#include <cuda_runtime.h>

// Shapes (fixed by the problem)
#define Bn   8
#define NIN  4096
#define DIN  128
#define KOUT 256

#define ADJ_TOTAL  (Bn * NIN * NIN)     // 134,217,728 floats (512 MB)

#define ADJ_BLOCKS 2048                 // 256 per batch
#define APB        (ADJ_BLOCKS / Bn)    // 256
#define NODE_BLOCKS 128                 // 16 per batch
#define NPB        (NODE_BLOCKS / Bn)   // 16
#define RTHREADS   256
#define BLOCKS_PER_BATCH (APB + NPB)    // 272

// Scratch — partials are fully overwritten each launch; the arrival counters
// are zero-initialized and reset to zero by the finisher block (deterministic).
__device__ float g_adj_part[ADJ_BLOCKS];
__device__ float g_node_part[NODE_BLOCKS * DIN];
__device__ int   g_count[Bn * 8];       // padded: one counter per 32B

// ---------------------------------------------------------------------------
// Single fused kernel.
//   blocks [0, ADJ_BLOCKS)            : partial total-sum of adj   (per batch)
//   blocks [ADJ_BLOCKS, +NODE_BLOCKS) : partial column-sum of node (per batch)
// The LAST block to arrive for a batch runs that batch's epilogue:
//   aval = sum(adj[b]);  row = lrelu(colsum(node[b]) @ lin_w + lin_b)
//   new_node_set[b,k,:] = row (all k);  new_adj[b,:,:] = aval (broadcast)
// (C == ones exactly: the reference softmax is over a size-1 axis.)
// ---------------------------------------------------------------------------
__global__ void mp_fused_kernel(const float* __restrict__ adj,
                                const float* __restrict__ node,
                                const float* __restrict__ lin_w,
                                const float* __restrict__ lin_b,
                                float* __restrict__ out) {
    const int bid = blockIdx.x;
    const int t   = threadIdx.x;
    int b;

    // All shared buffers 16B-aligned (r/c are read through float4).
    __shared__ __align__(16) float  sf[RTHREADS];
    __shared__ __align__(16) double sd[APB];     // 2 KB
    __shared__ __align__(16) float  c[DIN];
    __shared__ __align__(16) float  r[DIN];
    __shared__ int is_last;

    if (bid < ADJ_BLOCKS) {
        // ---- adj partial: contiguous 65536-float chunk ----
        b = bid / APB;
        const int f4pb = (ADJ_TOTAL / ADJ_BLOCKS) / 4;            // 16384
        const float4* __restrict__ base =
            reinterpret_cast<const float4*>(adj) + (size_t)bid * f4pb;

        float a0 = 0.0f, a1 = 0.0f;
        #pragma unroll 4
        for (int i = t; i < f4pb; i += 2 * RTHREADS) {
            float4 v0 = base[i];
            float4 v1 = base[i + RTHREADS];
            a0 += (v0.x + v0.y) + (v0.z + v0.w);
            a1 += (v1.x + v1.y) + (v1.z + v1.w);
        }
        sf[t] = a0 + a1;
        __syncthreads();
        for (int s = RTHREADS / 2; s > 0; s >>= 1) {
            if (t < s) sf[t] += sf[t + s];
            __syncthreads();
        }
        if (t == 0) g_adj_part[bid] = sf[0];
    } else {
        // ---- node partial colsum: 256 n-rows ----
        const int nb   = bid - ADJ_BLOCKS;                        // 0..127
        b = nb / NPB;
        const int sub  = nb % NPB;
        const int rows = NIN / NPB;                               // 256
        const float* __restrict__ base = node + ((size_t)b * NIN + sub * rows) * DIN;

        const int d      = t & (DIN - 1);
        const int stripe = t >> 7;

        float acc = 0.0f;
        #pragma unroll 4
        for (int rr = stripe * 128; rr < stripe * 128 + 128; rr++)
            acc += base[(size_t)rr * DIN + d];

        if (stripe == 0) sf[d] = acc;
        __syncthreads();
        if (stripe == 1) g_node_part[nb * DIN + d] = acc + sf[d];

        // Prefetch lin_w into L2 so the finisher's GEMV hits L2, not DRAM.
        {
            float w = lin_w[nb * DIN + d];
            asm volatile("" :: "f"(w));   // keep the load alive
        }
    }

    // ---- arrival: last block of this batch runs the epilogue ----
    __threadfence();
    __syncthreads();
    if (t == 0) {
        int old = atomicAdd(&g_count[b * 8], 1);
        is_last = (old == BLOCKS_PER_BATCH - 1);
    }
    __syncthreads();
    if (!is_last) return;

    // =================== epilogue for batch b ===================

    // total adj sum (256 partials, double accumulation)
    sd[t] = (double)g_adj_part[b * APB + t];
    __syncthreads();
    for (int s = APB / 2; s > 0; s >>= 1) {
        if (t < s) sd[t] += sd[t + s];
        __syncthreads();
    }
    const float aval = (float)sd[0];

    // colsum of node partials
    if (t < DIN) {
        float s = 0.0f;
        #pragma unroll
        for (int p = 0; p < NPB; p++)
            s += g_node_part[(b * NPB + p) * DIN + t];
        c[t] = s;
    }
    __syncthreads();

    // GEMV + leaky ReLU (load-batch-16 then FMA-batch-16 for MLP)
    if (t < DIN) {
        float acc = lin_b[t];
        #pragma unroll
        for (int d0 = 0; d0 < DIN; d0 += 16) {
            float w[16];
            #pragma unroll
            for (int j = 0; j < 16; j++) w[j] = lin_w[(d0 + j) * DIN + t];
            #pragma unroll
            for (int j = 0; j < 16; j++) acc = fmaf(c[d0 + j], w[j], acc);
        }
        r[t] = (acc >= 0.0f) ? acc : 0.01f * acc;
    }
    __syncthreads();

    // node region: batch b spans KOUT*DIN = 32768 floats = 8192 float4
    {
        float4* __restrict__ node_out =
            reinterpret_cast<float4*>(out) + (size_t)b * (KOUT * DIN / 4);
        const float4* __restrict__ r4 = reinterpret_cast<const float4*>(r);
        #pragma unroll 4
        for (int i = t; i < KOUT * DIN / 4; i += RTHREADS)
            node_out[i] = r4[i & (DIN / 4 - 1)];
    }

    // adj region: batch b spans KOUT*KOUT = 65536 floats = 16384 float4
    {
        float4* __restrict__ adj_out =
            reinterpret_cast<float4*>(out + (size_t)Bn * KOUT * DIN) +
            (size_t)b * (KOUT * KOUT / 4);
        const float4 av4 = make_float4(aval, aval, aval, aval);
        #pragma unroll 4
        for (int i = t; i < KOUT * KOUT / 4; i += RTHREADS)
            adj_out[i] = av4;
    }

    // reset counter for the next launch (only this block touches it now)
    if (t == 0) g_count[b * 8] = 0;
}

// ---------------------------------------------------------------------------
// Launch. Inputs (metadata order): node_set, adj, centroids, conv_w, conv_b,
// lin_w, lin_b. centroids/conv_* are mathematically dead (softmax over a
// size-1 axis makes C identically 1), so they are never read.
// ---------------------------------------------------------------------------
extern "C" void kernel_launch(void* const* d_in, const int* in_sizes, int n_in,
                              void* d_out, int out_size) {
    const float* node  = (const float*)d_in[0];
    const float* adj   = (const float*)d_in[1];
    const float* lin_w = (const float*)d_in[5];
    const float* lin_b = (const float*)d_in[6];
    float* out = (float*)d_out;

    mp_fused_kernel<<<ADJ_BLOCKS + NODE_BLOCKS, RTHREADS>>>(adj, node, lin_w, lin_b, out);
}

// round 5
// speedup vs baseline: 1.0865x; 1.0865x over previous
#include <cuda_runtime.h>

// Shapes (fixed by the problem)
#define Bn   8
#define NIN  4096
#define DIN  128
#define KOUT 256

#define ADJ_TOTAL  (Bn * NIN * NIN)     // 134,217,728 floats (512 MB)

#define ADJ_BLOCKS 2048                 // 256 per batch, 65536 floats each
#define APB        (ADJ_BLOCKS / Bn)    // 256
#define NODE_BLOCKS 128                 // 16 per batch
#define NPB        (NODE_BLOCKS / Bn)   // 16
#define RTHREADS   256

// Scratch — every slot fully overwritten each launch (deterministic, no init).
__device__ float  g_adj_part[ADJ_BLOCKS];
__device__ float  g_node_part[NODE_BLOCKS * DIN];
__device__ float  g_aval[Bn];
__device__ float4 g_row4[Bn][DIN / 4];  // lrelu(colsum @ lin_w + lin_b), 16B-aligned

// ---------------------------------------------------------------------------
// Kernel 1 (the 531 MB pass — kept LEAN; regs/occupancy are the speed knob).
//   blocks [0, ADJ_BLOCKS)            : partial total-sum of adj per batch
//   blocks [ADJ_BLOCKS, +NODE_BLOCKS) : partial colsum of node_set per batch
// C == ones exactly (reference softmax is over a size-1 axis), so these two
// reductions are the entire data-dependent work of the layer.
// ---------------------------------------------------------------------------
__global__ void __launch_bounds__(RTHREADS, 8)
mp_reduce_kernel(const float* __restrict__ adj,
                 const float* __restrict__ node,
                 const float* __restrict__ lin_w) {
    const int bid = blockIdx.x;
    const int t   = threadIdx.x;

    __shared__ float sf[RTHREADS];

    if (bid < ADJ_BLOCKS) {
        const int f4pb = (ADJ_TOTAL / ADJ_BLOCKS) / 4;            // 16384 float4
        const float4* __restrict__ base =
            reinterpret_cast<const float4*>(adj) + (size_t)bid * f4pb;

        // 4 independent accumulators -> 4 LDG.128 batched per iteration.
        float a0 = 0.f, a1 = 0.f, a2 = 0.f, a3 = 0.f;
        for (int i = t; i < f4pb; i += 4 * RTHREADS) {
            float4 v0 = base[i];
            float4 v1 = base[i + RTHREADS];
            float4 v2 = base[i + 2 * RTHREADS];
            float4 v3 = base[i + 3 * RTHREADS];
            a0 += (v0.x + v0.y) + (v0.z + v0.w);
            a1 += (v1.x + v1.y) + (v1.z + v1.w);
            a2 += (v2.x + v2.y) + (v2.z + v2.w);
            a3 += (v3.x + v3.y) + (v3.z + v3.w);
        }
        sf[t] = (a0 + a1) + (a2 + a3);
        __syncthreads();
        for (int s = RTHREADS / 2; s > 0; s >>= 1) {
            if (t < s) sf[t] += sf[t + s];
            __syncthreads();
        }
        if (t == 0) g_adj_part[bid] = sf[0];
    } else {
        // node partial colsum: 256 n-rows per block
        const int nb   = bid - ADJ_BLOCKS;                        // 0..127
        const int b    = nb / NPB;
        const int sub  = nb % NPB;
        const int rows = NIN / NPB;                               // 256
        const float* __restrict__ base = node + ((size_t)b * NIN + sub * rows) * DIN;

        const int d      = t & (DIN - 1);
        const int stripe = t >> 7;                                // 0 or 1

        float acc = 0.0f;
        #pragma unroll 4
        for (int r = stripe * 128; r < stripe * 128 + 128; r++)
            acc += base[(size_t)r * DIN + d];

        if (stripe == 0) sf[d] = acc;
        __syncthreads();
        if (stripe == 1) g_node_part[nb * DIN + d] = acc + sf[d];

        // Warm lin_w into L2 (128 blocks x 128 threads covers all 16384 elems)
        // so the scalar kernel's GEMV sees L2 hits, not cold DRAM.
        float w = lin_w[nb * DIN + d];
        asm volatile("" :: "f"(w));
    }
}

// ---------------------------------------------------------------------------
// Kernel 2: per-batch scalars (tiny, latency-optimized).
//   aval[b] = sum(adj[b]);  row[b] = lrelu(colsum(node[b]) @ lin_w + lin_b)
// GEMV latency chain split across 2 thread-halves (64 d each), combined in smem.
// ---------------------------------------------------------------------------
__global__ void mp_scalar_kernel(const float* __restrict__ lin_w,
                                 const float* __restrict__ lin_b) {
    const int b = blockIdx.x;
    const int t = threadIdx.x;

    __shared__ double sd[RTHREADS];
    __shared__ float  c[DIN];
    __shared__ float  part[RTHREADS];

    // adj total (256 partials, double tree)
    sd[t] = (double)g_adj_part[b * APB + t];
    __syncthreads();
    for (int s = RTHREADS / 2; s > 0; s >>= 1) {
        if (t < s) sd[t] += sd[t + s];
        __syncthreads();
    }
    if (t == 0) g_aval[b] = (float)sd[0];

    // colsum of node partials
    if (t < DIN) {
        float s = 0.0f;
        #pragma unroll
        for (int p = 0; p < NPB; p++)
            s += g_node_part[(b * NPB + p) * DIN + t];
        c[t] = s;
    }
    __syncthreads();

    // GEMV: thread t handles output j = t&127 over d-range half (t>>7).
    {
        const int j = t & (DIN - 1);
        const int h = t >> 7;
        float acc = 0.0f;
        #pragma unroll
        for (int d0 = h * 64; d0 < h * 64 + 64; d0 += 16) {
            float w[16];
            #pragma unroll
            for (int q = 0; q < 16; q++) w[q] = lin_w[(d0 + q) * DIN + j];
            #pragma unroll
            for (int q = 0; q < 16; q++) acc = fmaf(c[d0 + q], w[q], acc);
        }
        part[t] = acc;
    }
    __syncthreads();
    if (t < DIN) {
        float v = part[t] + part[t + 128] + lin_b[t];
        v = (v >= 0.0f) ? v : 0.01f * v;
        reinterpret_cast<float*>(g_row4)[b * DIN + t] = v;
    }
}

// ---------------------------------------------------------------------------
// Kernel 3: fill outputs (pure float4 stores, scalars are L2-hot).
//   new_node_set[b,k,:] = row[b]  (all k);  new_adj[b,:,:] = aval[b]
// 96 blocks per batch: 32 node (8192 f4) + 64 adj (16384 f4); 1 f4 per thread.
// ---------------------------------------------------------------------------
__global__ void mp_fill_kernel(float* __restrict__ out) {
    const int b = blockIdx.x / 96;
    const int s = blockIdx.x % 96;
    const int t = threadIdx.x;

    if (s < 32) {
        float4* __restrict__ node_out =
            reinterpret_cast<float4*>(out) + (size_t)b * (KOUT * DIN / 4);
        const int idx = s * RTHREADS + t;                 // 0..8191
        node_out[idx] = g_row4[b][idx & (DIN / 4 - 1)];
    } else {
        float4* __restrict__ adj_out =
            reinterpret_cast<float4*>(out + (size_t)Bn * KOUT * DIN) +
            (size_t)b * (KOUT * KOUT / 4);
        const float a = g_aval[b];
        adj_out[(s - 32) * RTHREADS + t] = make_float4(a, a, a, a);
    }
}

// ---------------------------------------------------------------------------
// Launch. Inputs (metadata order): node_set, adj, centroids, conv_w, conv_b,
// lin_w, lin_b. centroids/conv_* are mathematically dead (softmax over a
// size-1 axis makes C identically 1), so they are never read.
// ---------------------------------------------------------------------------
extern "C" void kernel_launch(void* const* d_in, const int* in_sizes, int n_in,
                              void* d_out, int out_size) {
    const float* node  = (const float*)d_in[0];
    const float* adj   = (const float*)d_in[1];
    const float* lin_w = (const float*)d_in[5];
    const float* lin_b = (const float*)d_in[6];
    float* out = (float*)d_out;

    mp_reduce_kernel<<<ADJ_BLOCKS + NODE_BLOCKS, RTHREADS>>>(adj, node, lin_w);
    mp_scalar_kernel<<<Bn, RTHREADS>>>(lin_w, lin_b);
    mp_fill_kernel<<<Bn * 96, RTHREADS>>>(out);
}

// round 6
// speedup vs baseline: 1.1988x; 1.1033x over previous
#include <cuda_runtime.h>

// Shapes (fixed by the problem)
#define Bn   8
#define NIN  4096
#define DIN  128
#define KOUT 256

#define ADJ_TOTAL  (Bn * NIN * NIN)     // 134,217,728 floats (512 MB)

// Single-wave geometry: 1024 + 128 = 1152 CTAs <= 148 SMs * 8 CTAs = 1184.
#define ADJ_BLOCKS 1024                 // 128 per batch, 131072 floats each
#define APB        (ADJ_BLOCKS / Bn)    // 128
#define NODE_BLOCKS 128                 // 16 per batch
#define NPB        (NODE_BLOCKS / Bn)   // 16
#define RTHREADS   256

// Scratch — every slot fully overwritten each launch (deterministic, no init).
__device__ float g_adj_part[ADJ_BLOCKS];
__device__ float g_node_part[NODE_BLOCKS * DIN];

// ---------------------------------------------------------------------------
// Kernel 1 (the 531 MB pass — lean, 8 CTAs/SM, exactly one wave).
//   blocks [0, ADJ_BLOCKS)            : partial total-sum of adj per batch
//   blocks [ADJ_BLOCKS, +NODE_BLOCKS) : partial colsum of node_set per batch
// C == ones exactly (reference softmax is over a size-1 axis), so these two
// reductions are the entire data-dependent work of the layer.
// ---------------------------------------------------------------------------
__global__ void __launch_bounds__(RTHREADS, 8)
mp_reduce_kernel(const float* __restrict__ adj,
                 const float* __restrict__ node,
                 const float* __restrict__ lin_w) {
    const int bid = blockIdx.x;
    const int t   = threadIdx.x;

    __shared__ __align__(16) float sf[RTHREADS];

    if (bid < ADJ_BLOCKS) {
        const int f4pb = (ADJ_TOTAL / ADJ_BLOCKS) / 4;            // 32768 float4
        const float4* __restrict__ base =
            reinterpret_cast<const float4*>(adj) + (size_t)bid * f4pb;

        // 4 independent accumulators, streaming loads (single-use data).
        float a0 = 0.f, a1 = 0.f, a2 = 0.f, a3 = 0.f;
        for (int i = t; i < f4pb; i += 4 * RTHREADS) {
            float4 v0 = __ldcs(base + i);
            float4 v1 = __ldcs(base + i + RTHREADS);
            float4 v2 = __ldcs(base + i + 2 * RTHREADS);
            float4 v3 = __ldcs(base + i + 3 * RTHREADS);
            a0 += (v0.x + v0.y) + (v0.z + v0.w);
            a1 += (v1.x + v1.y) + (v1.z + v1.w);
            a2 += (v2.x + v2.y) + (v2.z + v2.w);
            a3 += (v3.x + v3.y) + (v3.z + v3.w);
        }
        sf[t] = (a0 + a1) + (a2 + a3);
        __syncthreads();
        for (int s = RTHREADS / 2; s > 0; s >>= 1) {
            if (t < s) sf[t] += sf[t + s];
            __syncthreads();
        }
        if (t == 0) g_adj_part[bid] = sf[0];
    } else {
        // node partial colsum: 256 n-rows per block
        const int nb   = bid - ADJ_BLOCKS;                        // 0..127
        const int b    = nb / NPB;
        const int sub  = nb % NPB;
        const int rows = NIN / NPB;                               // 256
        const float* __restrict__ base = node + ((size_t)b * NIN + sub * rows) * DIN;

        const int d      = t & (DIN - 1);
        const int stripe = t >> 7;                                // 0 or 1

        float acc = 0.0f;
        #pragma unroll 4
        for (int r = stripe * 128; r < stripe * 128 + 128; r++)
            acc += base[(size_t)r * DIN + d];

        if (stripe == 0) sf[d] = acc;
        __syncthreads();
        if (stripe == 1) g_node_part[nb * DIN + d] = acc + sf[d];

        // Warm lin_w into L2 so the tail kernel's GEMVs hit L2, not DRAM.
        float w = lin_w[nb * DIN + d];
        asm volatile("" :: "f"(w));
    }
}

// ---------------------------------------------------------------------------
// Kernel 2 (tail, PDL): 96 blocks per batch.
//   s in [0,32):  node fill — recompute colsum+GEMV from L2-hot partials,
//                 write 256 float4 of new_node_set[b].
//   s in [32,96): adj fill — recompute aval from 128 L2-hot partials,
//                 write 256 float4 of new_adj[b].
// Redundant per-block recompute is identical FP order everywhere -> deterministic.
// ---------------------------------------------------------------------------
__global__ void __launch_bounds__(RTHREADS)
mp_tail_kernel(const float* __restrict__ lin_w,
               const float* __restrict__ lin_b,
               float* __restrict__ out) {
#if __CUDA_ARCH__ >= 900
    cudaGridDependencySynchronize();   // PDL: wait for mp_reduce_kernel
#endif
    const int b = blockIdx.x / 96;
    const int s = blockIdx.x % 96;
    const int t = threadIdx.x;

    if (s < 32) {
        // ---- node region ----
        __shared__ __align__(16) float c[DIN];
        __shared__ __align__(16) float part[RTHREADS];
        __shared__ __align__(16) float r[DIN];

        if (t < DIN) {
            float acc = 0.0f;
            #pragma unroll
            for (int p = 0; p < NPB; p++)
                acc += g_node_part[(b * NPB + p) * DIN + t];
            c[t] = acc;
        }
        __syncthreads();

        // GEMV split across 2 thread-halves (64 d each)
        {
            const int j = t & (DIN - 1);
            const int h = t >> 7;
            float acc = 0.0f;
            #pragma unroll
            for (int d0 = h * 64; d0 < h * 64 + 64; d0 += 16) {
                float w[16];
                #pragma unroll
                for (int q = 0; q < 16; q++) w[q] = lin_w[(d0 + q) * DIN + j];
                #pragma unroll
                for (int q = 0; q < 16; q++) acc = fmaf(c[d0 + q], w[q], acc);
            }
            part[t] = acc;
        }
        __syncthreads();
        if (t < DIN) {
            float v = part[t] + part[t + 128] + lin_b[t];
            r[t] = (v >= 0.0f) ? v : 0.01f * v;
        }
        __syncthreads();

        float4* __restrict__ node_out =
            reinterpret_cast<float4*>(out) + (size_t)b * (KOUT * DIN / 4);
        const float4* __restrict__ r4 = reinterpret_cast<const float4*>(r);
        const int idx = s * RTHREADS + t;              // 0..8191
        node_out[idx] = r4[idx & (DIN / 4 - 1)];
    } else {
        // ---- adj region ----
        __shared__ __align__(16) double sd[APB];       // 128 doubles

        if (t < APB) sd[t] = (double)g_adj_part[b * APB + t];
        __syncthreads();
        for (int k = APB / 2; k > 0; k >>= 1) {
            if (t < k) sd[t] += sd[t + k];
            __syncthreads();
        }
        const float a = (float)sd[0];

        float4* __restrict__ adj_out =
            reinterpret_cast<float4*>(out + (size_t)Bn * KOUT * DIN) +
            (size_t)b * (KOUT * KOUT / 4);
        adj_out[(s - 32) * RTHREADS + t] = make_float4(a, a, a, a);
    }
}

// ---------------------------------------------------------------------------
// Launch. Inputs (metadata order): node_set, adj, centroids, conv_w, conv_b,
// lin_w, lin_b. centroids/conv_* are mathematically dead (softmax over a
// size-1 axis makes C identically 1), so they are never read.
// ---------------------------------------------------------------------------
extern "C" void kernel_launch(void* const* d_in, const int* in_sizes, int n_in,
                              void* d_out, int out_size) {
    const float* node  = (const float*)d_in[0];
    const float* adj   = (const float*)d_in[1];
    const float* lin_w = (const float*)d_in[5];
    const float* lin_b = (const float*)d_in[6];
    float* out = (float*)d_out;

    mp_reduce_kernel<<<ADJ_BLOCKS + NODE_BLOCKS, RTHREADS>>>(adj, node, lin_w);

    // Tail with programmatic dependent launch (overlaps launch with reduce drain).
    cudaLaunchConfig_t cfg = {};
    cfg.gridDim  = dim3(Bn * 96);
    cfg.blockDim = dim3(RTHREADS);
    cfg.dynamicSmemBytes = 0;
    cfg.stream = 0;
    cudaLaunchAttribute attr[1];
    attr[0].id = cudaLaunchAttributeProgrammaticStreamSerialization;
    attr[0].val.programmaticStreamSerializationAllowed = 1;
    cfg.attrs = attr;
    cfg.numAttrs = 1;
    cudaLaunchKernelEx(&cfg, mp_tail_kernel, lin_w, lin_b, out);
}

// round 7
// speedup vs baseline: 1.2133x; 1.0121x over previous
#include <cuda_runtime.h>

// Shapes (fixed by the problem)
#define Bn   8
#define NIN  4096
#define DIN  128
#define KOUT 256

#define ADJ_TOTAL  (Bn * NIN * NIN)     // 134,217,728 floats (512 MB)

// Single-wave geometry: 1024 + 128 = 1152 CTAs <= 148 SMs * 8 CTAs = 1184.
#define ADJ_BLOCKS 1024                 // 128 per batch, 131072 floats each
#define APB        (ADJ_BLOCKS / Bn)    // 128
#define NODE_BLOCKS 128                 // 16 per batch
#define NPB        (NODE_BLOCKS / Bn)   // 16
#define RTHREADS   256

// Scratch — every slot fully overwritten each launch (deterministic, no init).
__device__ float g_adj_part[ADJ_BLOCKS];
__device__ float g_node_part[NODE_BLOCKS * DIN];

// ---------------------------------------------------------------------------
// Kernel 1 (the 531 MB pass — PROTECTED: 29 regs, 8 CTAs/SM, one wave,
// 6.5 TB/s measured; do not disturb).
//   blocks [0, ADJ_BLOCKS)            : partial total-sum of adj per batch
//   blocks [ADJ_BLOCKS, +NODE_BLOCKS) : partial colsum of node_set per batch
// C == ones exactly (reference softmax is over a size-1 axis), so these two
// reductions are the entire data-dependent work of the layer.
// ---------------------------------------------------------------------------
__global__ void __launch_bounds__(RTHREADS, 8)
mp_reduce_kernel(const float* __restrict__ adj,
                 const float* __restrict__ node,
                 const float* __restrict__ lin_w) {
    const int bid = blockIdx.x;
    const int t   = threadIdx.x;

    __shared__ __align__(16) float sf[RTHREADS];

    if (bid < ADJ_BLOCKS) {
        const int f4pb = (ADJ_TOTAL / ADJ_BLOCKS) / 4;            // 32768 float4
        const float4* __restrict__ base =
            reinterpret_cast<const float4*>(adj) + (size_t)bid * f4pb;

        // 4 independent accumulators, streaming loads (single-use data).
        float a0 = 0.f, a1 = 0.f, a2 = 0.f, a3 = 0.f;
        for (int i = t; i < f4pb; i += 4 * RTHREADS) {
            float4 v0 = __ldcs(base + i);
            float4 v1 = __ldcs(base + i + RTHREADS);
            float4 v2 = __ldcs(base + i + 2 * RTHREADS);
            float4 v3 = __ldcs(base + i + 3 * RTHREADS);
            a0 += (v0.x + v0.y) + (v0.z + v0.w);
            a1 += (v1.x + v1.y) + (v1.z + v1.w);
            a2 += (v2.x + v2.y) + (v2.z + v2.w);
            a3 += (v3.x + v3.y) + (v3.z + v3.w);
        }
        sf[t] = (a0 + a1) + (a2 + a3);
        __syncthreads();
        for (int s = RTHREADS / 2; s > 0; s >>= 1) {
            if (t < s) sf[t] += sf[t + s];
            __syncthreads();
        }
        if (t == 0) g_adj_part[bid] = sf[0];
    } else {
        // node partial colsum: 256 n-rows per block
        const int nb   = bid - ADJ_BLOCKS;                        // 0..127
        const int b    = nb / NPB;
        const int sub  = nb % NPB;
        const int rows = NIN / NPB;                               // 256
        const float* __restrict__ base = node + ((size_t)b * NIN + sub * rows) * DIN;

        const int d      = t & (DIN - 1);
        const int stripe = t >> 7;                                // 0 or 1

        float acc = 0.0f;
        #pragma unroll 4
        for (int r = stripe * 128; r < stripe * 128 + 128; r++)
            acc += base[(size_t)r * DIN + d];

        if (stripe == 0) sf[d] = acc;
        __syncthreads();
        if (stripe == 1) g_node_part[nb * DIN + d] = acc + sf[d];

        // Warm lin_w into L2 so the tail kernel's GEMVs hit L2, not DRAM.
        float w = lin_w[nb * DIN + d];
        asm volatile("" :: "f"(w));
    }
}

// ---------------------------------------------------------------------------
// Kernel 2 (tail, PDL): 96 blocks per batch; minimal-barrier critical path.
//   s in [0,32):  node fill — colsum + GEMV from L2-hot partials (2 barriers),
//                 write 256 float4 of new_node_set[b].
//   s in [32,96): adj fill — shuffle-reduce 128 L2-hot partials (1 barrier),
//                 write 256 float4 of new_adj[b].
// Every block of a batch computes in the identical FP order -> deterministic.
// ---------------------------------------------------------------------------
__global__ void __launch_bounds__(RTHREADS)
mp_tail_kernel(const float* __restrict__ lin_w,
               const float* __restrict__ lin_b,
               float* __restrict__ out) {
#if __CUDA_ARCH__ >= 900
    cudaGridDependencySynchronize();   // PDL: wait for mp_reduce_kernel
#endif
    const int b = blockIdx.x / 96;
    const int s = blockIdx.x % 96;
    const int t = threadIdx.x;

    if (s < 32) {
        // ---- node region ----
        __shared__ __align__(16) float c[DIN];
        __shared__ __align__(16) float r[DIN];

        if (t < DIN) {
            float acc = 0.0f;
            #pragma unroll
            for (int p = 0; p < NPB; p++)
                acc += g_node_part[(b * NPB + p) * DIN + t];
            c[t] = acc;
        }
        __syncthreads();                               // barrier 1

        if (t < DIN) {
            // GEMV: 4 independent accumulators over the 128-d chain.
            float a0 = 0.f, a1 = 0.f, a2 = 0.f, a3 = 0.f;
            #pragma unroll
            for (int q = 0; q < 32; q++) {
                a0 = fmaf(c[q],      lin_w[(q)      * DIN + t], a0);
                a1 = fmaf(c[q + 32], lin_w[(q + 32) * DIN + t], a1);
                a2 = fmaf(c[q + 64], lin_w[(q + 64) * DIN + t], a2);
                a3 = fmaf(c[q + 96], lin_w[(q + 96) * DIN + t], a3);
            }
            float v = ((a0 + a1) + (a2 + a3)) + lin_b[t];
            r[t] = (v >= 0.0f) ? v : 0.01f * v;
        }
        __syncthreads();                               // barrier 2

        float4* __restrict__ node_out =
            reinterpret_cast<float4*>(out) + (size_t)b * (KOUT * DIN / 4);
        const float4* __restrict__ r4 = reinterpret_cast<const float4*>(r);
        const int idx = s * RTHREADS + t;              // 0..8191
        node_out[idx] = r4[idx & (DIN / 4 - 1)];
    } else {
        // ---- adj region: shuffle-reduce the 128 partials ----
        __shared__ float ws[4];

        float v = (t < APB) ? g_adj_part[b * APB + t] : 0.0f;
        #pragma unroll
        for (int off = 16; off > 0; off >>= 1)
            v += __shfl_xor_sync(0xffffffffu, v, off);
        if (t < APB && (t & 31) == 0) ws[t >> 5] = v;  // warps 0..3
        __syncthreads();                               // barrier 1
        const float a = (ws[0] + ws[1]) + (ws[2] + ws[3]);

        float4* __restrict__ adj_out =
            reinterpret_cast<float4*>(out + (size_t)Bn * KOUT * DIN) +
            (size_t)b * (KOUT * KOUT / 4);
        adj_out[(s - 32) * RTHREADS + t] = make_float4(a, a, a, a);
    }
}

// ---------------------------------------------------------------------------
// Launch. Inputs (metadata order): node_set, adj, centroids, conv_w, conv_b,
// lin_w, lin_b. centroids/conv_* are mathematically dead (softmax over a
// size-1 axis makes C identically 1), so they are never read.
// ---------------------------------------------------------------------------
extern "C" void kernel_launch(void* const* d_in, const int* in_sizes, int n_in,
                              void* d_out, int out_size) {
    const float* node  = (const float*)d_in[0];
    const float* adj   = (const float*)d_in[1];
    const float* lin_w = (const float*)d_in[5];
    const float* lin_b = (const float*)d_in[6];
    float* out = (float*)d_out;

    mp_reduce_kernel<<<ADJ_BLOCKS + NODE_BLOCKS, RTHREADS>>>(adj, node, lin_w);

    // Tail with programmatic dependent launch (overlaps launch with reduce drain).
    cudaLaunchConfig_t cfg = {};
    cfg.gridDim  = dim3(Bn * 96);
    cfg.blockDim = dim3(RTHREADS);
    cfg.dynamicSmemBytes = 0;
    cfg.stream = 0;
    cudaLaunchAttribute attr[1];
    attr[0].id = cudaLaunchAttributeProgrammaticStreamSerialization;
    attr[0].val.programmaticStreamSerializationAllowed = 1;
    cfg.attrs = attr;
    cfg.numAttrs = 1;
    cudaLaunchKernelEx(&cfg, mp_tail_kernel, lin_w, lin_b, out);
}